// round 10
// baseline (speedup 1.0000x reference)
#include <cuda_runtime.h>
#include <cuda_fp16.h>

#define IMG_H 4096
#define IMG_W 4096
#define OUT_H 4097
#define OUT_W 4097
#define TILE  32
#define HIST  35   // TILE + 3
#define INW   37   // HIST + 2 (sobel halo)
#define INP   38   // padded input row stride (words)
#define HP    37   // s_pk row stride (uint2)
#define RSU   36   // s_rs row stride (uint4)

__device__ __forceinline__ unsigned int hadd2u(unsigned int a, unsigned int b) {
    __half2 ha = *reinterpret_cast<__half2*>(&a);
    __half2 hb = *reinterpret_cast<__half2*>(&b);
    __half2 hr = __hadd2(ha, hb);
    return *reinterpret_cast<unsigned int*>(&hr);
}
__device__ __forceinline__ float2 h2f2u(unsigned int a) {
    __half2 h = *reinterpret_cast<__half2*>(&a);
    return __half22float2(h);
}
__device__ __forceinline__ uint4 u4add(uint4 a, uint4 b) {
    return make_uint4(hadd2u(a.x, b.x), hadd2u(a.y, b.y),
                      hadd2u(a.z, b.z), hadd2u(a.w, b.w));
}

__global__ __launch_bounds__(256, 6)
void sift_fused_kernel(const float* __restrict__ x, float* __restrict__ out)
{
    // rs: [hist row][x] of 8 x fp16 channel row-sums; lane(x) contiguous uint4.
    __shared__ uint4 s_rs[HIST][RSU];   // 20160 B (aliased as input tile)
    __shared__ uint2 s_pk[HIST][HP];    // 10360 B  (msh, pair-id)
    // total 30520 B -> 6 CTAs/SM

    float* s_in = (float*)s_rs;   // [INW][INP] = 5624 B, dead after stage 2

    const int X0   = blockIdx.x * TILE;
    const int Y0   = blockIdx.y * TILE;
    const int tid  = threadIdx.x;
    const int lane = tid & 31;
    const int wrow = tid >> 5;    // 0..7

    const bool interior =
        blockIdx.x >= 1 && blockIdx.x <= 126 &&
        blockIdx.y >= 1 && blockIdx.y <= 126;

    // ---- Stage 1: load input tile (origin Y0-3, X0-3) ----
    if (interior) {
        const float* src = x + (size_t)(Y0 - 3) * IMG_W + (X0 - 3);
        #pragma unroll
        for (int it = 0; it < 5; ++it) {
            int r = wrow + 8 * it;
            if (r < INW) {
                const float* row = src + (size_t)r * IMG_W;
                s_in[r * INP + lane] = row[lane];
                if (lane < INW - 32)
                    s_in[r * INP + 32 + lane] = row[32 + lane];
            }
        }
    } else {
        #pragma unroll
        for (int it = 0; it < 5; ++it) {
            int r = wrow + 8 * it;
            if (r < INW) {
                int  gy    = Y0 - 3 + r;
                bool rowok = (gy >= 0) && (gy < IMG_H);
                int  gx    = X0 - 3 + lane;
                float v = 0.0f;
                if (rowok && gx >= 0 && gx < IMG_W)
                    v = x[(size_t)gy * IMG_W + gx];
                s_in[r * INP + lane] = v;
                if (lane < INW - 32) {
                    int gx2 = gx + 32;
                    float v2 = 0.0f;
                    if (rowok && gx2 >= 0 && gx2 < IMG_W)
                        v2 = x[(size_t)gy * IMG_W + gx2];
                    s_in[r * INP + 32 + lane] = v2;
                }
            }
        }
    }
    __syncthreads();

    // ---- Stage 2: column-sliding Sobel + octant bin + packed store ----
    // 35 columns x 7 strips of 5 rows = 245 segments; rolling row stats.
    if (tid < 245) {
        int col   = tid % 35;
        int strip = tid / 35;
        int h0    = strip * 5;
        const float* base = s_in + h0 * INP + col;

        float c0 = base[0],       c1 = base[1],       c2 = base[2];
        float d0 = c2 - c0;
        float s0 = fmaf(2.0f, c1, c0) + c2;
        c0 = base[INP]; c1 = base[INP + 1]; c2 = base[INP + 2];
        float d1 = c2 - c0;
        float s1 = fmaf(2.0f, c1, c0) + c2;

        const int  gx    = X0 - 2 + col;
        const bool colok = (gx >= 0) && (gx < IMG_W);

        #pragma unroll
        for (int r = 0; r < 5; ++r) {
            const float* rb = base + (r + 2) * INP;
            c0 = rb[0]; c1 = rb[1]; c2 = rb[2];
            float d2 = c2 - c0;
            float s2 = fmaf(2.0f, c1, c0) + c2;

            float dx = fmaf(2.0f, d1, d0) + d2;
            float dy = s2 - s0;

            // octant bin == argmax over 8 orientation cosines
            unsigned int sx = __float_as_uint(dx) >> 31;
            unsigned int sy = __float_as_uint(dy) >> 31;
            unsigned int tb = (fabsf(dy) > fabsf(dx)) ? 1u : 0u;
            unsigned int e  = sx ^ sy;
            unsigned int bi = (sy << 2) | (e << 1) | (e ^ tb);

            float m2  = fmaf(dx, dx, dy * dy);
            float mag = m2 * rsqrtf(fmaxf(m2, 1e-35f));

            unsigned int mh  = (unsigned int)__half_as_ushort(__float2half_rn(mag));
            unsigned int msh = mh << ((bi & 1u) << 4);
            unsigned int w   = bi >> 1;

            if (!interior) {
                int gy = Y0 - 2 + h0 + r;
                if (!(colok && gy >= 0 && gy < IMG_H)) { msh = 0u; w = 0u; }
            }
            s_pk[h0 + r][col] = make_uint2(msh, w);

            d0 = d1; d1 = d2;
            s0 = s1; s1 = s2;
        }
    }
    __syncthreads();

    // ---- Stage 3: horizontal 4-tap row sums, shift-scatter into fp16 ----
    #pragma unroll
    for (int it = 0; it < 5; ++it) {
        int e = tid + 256 * it;
        if (e < HIST * TILE) {
            int h  = e >> 5;
            int ox = e & 31;
            unsigned int a0 = 0u, a1 = 0u, a2 = 0u, a3 = 0u;
            #pragma unroll
            for (int k = 0; k < 4; k++) {
                uint2 u = s_pk[h][ox + k];
                if (u.y == 0u) a0 = hadd2u(a0, u.x);
                if (u.y == 1u) a1 = hadd2u(a1, u.x);
                if (u.y == 2u) a2 = hadd2u(a2, u.x);
                if (u.y == 3u) a3 = hadd2u(a3, u.x);
            }
            s_rs[h][ox] = make_uint4(a0, a1, a2, a3);
        }
    }
    __syncthreads();

    // ---- Stage 4: vertical 4-tap pair tree (fp16) + store 8 channels ----
    const int    gx    = X0 + lane;
    const size_t plane = (size_t)OUT_H * OUT_W;
    const int    oy0   = wrow * 4;          // 4 consecutive output rows

    uint4 r0 = s_rs[oy0][lane];
    uint4 r1 = s_rs[oy0 + 1][lane];
    uint4 r2 = s_rs[oy0 + 2][lane];
    uint4 r3 = s_rs[oy0 + 3][lane];
    uint4 r4 = s_rs[oy0 + 4][lane];
    uint4 r5 = s_rs[oy0 + 5][lane];
    uint4 r6 = s_rs[oy0 + 6][lane];

    uint4 p0 = u4add(r0, r1);
    uint4 p1 = u4add(r1, r2);
    uint4 p2 = u4add(r2, r3);
    uint4 p3 = u4add(r3, r4);
    uint4 p4 = u4add(r4, r5);
    uint4 p5 = u4add(r5, r6);

    uint4 o0 = u4add(p0, p2);
    uint4 o1 = u4add(p1, p3);
    uint4 o2 = u4add(p2, p4);
    uint4 o3 = u4add(p3, p5);

    #define EMIT(OV, R) do {                                              \
        int gy = Y0 + oy0 + (R);                                          \
        if (gy < OUT_H && gx < OUT_W) {                                   \
            uint4 _o = (OV);                                              \
            size_t base = (size_t)gy * OUT_W + gx;                        \
            float2 f0 = h2f2u(_o.x); float2 f1 = h2f2u(_o.y);             \
            float2 f2 = h2f2u(_o.z); float2 f3 = h2f2u(_o.w);             \
            out[base]             = f0.x;                                 \
            out[plane + base]     = f0.y;                                 \
            out[2 * plane + base] = f1.x;                                 \
            out[3 * plane + base] = f1.y;                                 \
            out[4 * plane + base] = f2.x;                                 \
            out[5 * plane + base] = f2.y;                                 \
            out[6 * plane + base] = f3.x;                                 \
            out[7 * plane + base] = f3.y;                                 \
        }                                                                 \
    } while (0)

    EMIT(o0, 0);
    EMIT(o1, 1);
    EMIT(o2, 2);
    EMIT(o3, 3);
    #undef EMIT
}

extern "C" void kernel_launch(void* const* d_in, const int* in_sizes, int n_in,
                              void* d_out, int out_size)
{
    const float* x   = (const float*)d_in[0];
    float*       out = (float*)d_out;
    dim3 grid((OUT_W + TILE - 1) / TILE, (OUT_H + TILE - 1) / TILE);  // 129 x 129
    sift_fused_kernel<<<grid, 256>>>(x, out);
}

// round 11
// speedup vs baseline: 1.1026x; 1.1026x over previous
#include <cuda_runtime.h>
#include <cuda_bf16.h>

#define IMG_H 4096
#define IMG_W 4096
#define OUT_H 4097
#define OUT_W 4097
#define TILE  32
#define HIST  35   // TILE + 3
#define INW   37   // HIST + 2 (sobel halo)
#define INP   38   // padded input row stride (words)
#define HP    37   // packed (mag|idx) row stride (odd)

__device__ __forceinline__ float4 f4add(float4 a, float4 b) {
    return make_float4(a.x + b.x, a.y + b.y, a.z + b.z, a.w + b.w);
}
__device__ __forceinline__ float4 f4addsub(float4 a, float4 p, float4 m) {
    return make_float4(a.x + p.x - m.x, a.y + p.y - m.y,
                       a.z + p.z - m.z, a.w + p.w - m.w);
}

__global__ __launch_bounds__(256, 5)
void sift_fused_kernel(const float* __restrict__ x, float* __restrict__ out)
{
    // rs: [chan-group][hist row][x] -> lane(x) contiguous float4 (champion layout)
    __shared__ float4       s_rs[2][HIST][TILE];  // 35840 B (aliased as input tile)
    __shared__ unsigned int s_pk[HIST][HP];       //  5180 B packed mag|idx
    // total 41020 B -> 5 CTAs/SM

    float* s_in = (float*)s_rs;   // [INW][INP] = 5624 B, dead after stage 2

    const int X0   = blockIdx.x * TILE;
    const int Y0   = blockIdx.y * TILE;
    const int tid  = threadIdx.x;
    const int lane = tid & 31;
    const int wrow = tid >> 5;    // 0..7

    const bool interior =
        blockIdx.x >= 1 && blockIdx.x <= 126 &&
        blockIdx.y >= 1 && blockIdx.y <= 126;

    // ---- Stage 1: load input tile (origin Y0-3, X0-3) ----
    if (interior) {
        const float* src = x + (size_t)(Y0 - 3) * IMG_W + (X0 - 3);
        #pragma unroll
        for (int it = 0; it < 5; ++it) {
            int r = wrow + 8 * it;
            if (r < INW) {
                const float* row = src + (size_t)r * IMG_W;
                s_in[r * INP + lane] = row[lane];
                if (lane < INW - 32)
                    s_in[r * INP + 32 + lane] = row[32 + lane];
            }
        }
    } else {
        #pragma unroll
        for (int it = 0; it < 5; ++it) {
            int r = wrow + 8 * it;
            if (r < INW) {
                int  gy    = Y0 - 3 + r;
                bool rowok = (gy >= 0) && (gy < IMG_H);
                int  gx    = X0 - 3 + lane;
                float v = 0.0f;
                if (rowok && gx >= 0 && gx < IMG_W)
                    v = x[(size_t)gy * IMG_W + gx];
                s_in[r * INP + lane] = v;
                if (lane < INW - 32) {
                    int gx2 = gx + 32;
                    float v2 = 0.0f;
                    if (rowok && gx2 >= 0 && gx2 < IMG_W)
                        v2 = x[(size_t)gy * IMG_W + gx2];
                    s_in[r * INP + 32 + lane] = v2;
                }
            }
        }
    }
    __syncthreads();

    // ---- Stage 2: flat per-pixel Sobel + octant bin + packed store ----
    #pragma unroll
    for (int it = 0; it < 5; ++it) {
        int e = tid + 256 * it;
        if (e < HIST * HIST) {
            int h = e / HIST, w = e % HIST;
            const float* c = s_in + h * INP + w;
            float a00 = c[0],       a01 = c[1],           a02 = c[2];
            float a10 = c[INP],                            a12 = c[INP + 2];
            float a20 = c[2*INP],   a21 = c[2*INP + 1],   a22 = c[2*INP + 2];

            float dx = (a02 - a00) + 2.0f * (a12 - a10) + (a22 - a20);
            float dy = (a20 - a00) + 2.0f * (a21 - a01) + (a22 - a02);

            // octant bin == argmax over the 8 orientation cosines
            unsigned int sx = __float_as_uint(dx) >> 31;
            unsigned int sy = __float_as_uint(dy) >> 31;
            unsigned int tb = (fabsf(dy) > fabsf(dx)) ? 1u : 0u;
            unsigned int ex = sx ^ sy;
            unsigned int bi = (sy << 2) | (ex << 1) | (ex ^ tb);

            float m2  = fmaf(dx, dx, dy * dy);
            float mag = m2 * rsqrtf(fmaxf(m2, 1e-35f));

            unsigned int bits = (__float_as_uint(mag) & 0xFFFFFFF8u) | bi;

            if (!interior) {
                int gy = Y0 - 2 + h;
                int gx = X0 - 2 + w;
                if (!(gy >= 0 && gy < IMG_H && gx >= 0 && gx < IMG_W)) bits = 0u;
            }
            s_pk[h][w] = bits;
        }
    }
    __syncthreads();

    // ---- Stage 3: horizontal 4-tap row sums with one-hot scatter ----
    // rs[c][h][x] = sum_{k=0..3} hist_c(h, x+k)  (champion mapping)
    #pragma unroll
    for (int it = 0; it < 5; ++it) {
        int e = tid + 256 * it;
        if (e < HIST * TILE) {
            int h  = e >> 5;
            int ox = e & 31;
            float a0 = 0.f, a1 = 0.f, a2 = 0.f, a3 = 0.f;
            float a4 = 0.f, a5 = 0.f, a6 = 0.f, a7 = 0.f;
            #pragma unroll
            for (int k = 0; k < 4; k++) {
                unsigned int u = s_pk[h][ox + k];
                unsigned int i = u & 7u;
                float m = __uint_as_float(u);   // idx bits: <=2^-21 rel noise
                if (i == 0u) a0 += m;
                if (i == 1u) a1 += m;
                if (i == 2u) a2 += m;
                if (i == 3u) a3 += m;
                if (i == 4u) a4 += m;
                if (i == 5u) a5 += m;
                if (i == 6u) a6 += m;
                if (i == 7u) a7 += m;
            }
            s_rs[0][h][ox] = make_float4(a0, a1, a2, a3);
            s_rs[1][h][ox] = make_float4(a4, a5, a6, a7);
        }
    }
    __syncthreads();

    // ---- Stage 4: vertical 4-tap sliding sum + store 8 channels (champion) ----
    const int    gx    = X0 + lane;
    const size_t plane = (size_t)OUT_H * OUT_W;
    const int    oy0   = wrow * 4;          // 4 consecutive rows per thread

    float4 lo = f4add(f4add(s_rs[0][oy0][lane],     s_rs[0][oy0 + 1][lane]),
                      f4add(s_rs[0][oy0 + 2][lane], s_rs[0][oy0 + 3][lane]));
    float4 hi = f4add(f4add(s_rs[1][oy0][lane],     s_rs[1][oy0 + 1][lane]),
                      f4add(s_rs[1][oy0 + 2][lane], s_rs[1][oy0 + 3][lane]));

    #pragma unroll
    for (int r = 0; r < 4; r++) {
        if (r > 0) {
            lo = f4addsub(lo, s_rs[0][oy0 + r + 3][lane], s_rs[0][oy0 + r - 1][lane]);
            hi = f4addsub(hi, s_rs[1][oy0 + r + 3][lane], s_rs[1][oy0 + r - 1][lane]);
        }
        int gy = Y0 + oy0 + r;
        if (gy < OUT_H && gx < OUT_W) {
            size_t base = (size_t)gy * OUT_W + gx;
            out[0 * plane + base] = lo.x;
            out[1 * plane + base] = lo.y;
            out[2 * plane + base] = lo.z;
            out[3 * plane + base] = lo.w;
            out[4 * plane + base] = hi.x;
            out[5 * plane + base] = hi.y;
            out[6 * plane + base] = hi.z;
            out[7 * plane + base] = hi.w;
        }
    }
}

extern "C" void kernel_launch(void* const* d_in, const int* in_sizes, int n_in,
                              void* d_out, int out_size)
{
    const float* x   = (const float*)d_in[0];
    float*       out = (float*)d_out;
    dim3 grid((OUT_W + TILE - 1) / TILE, (OUT_H + TILE - 1) / TILE);  // 129 x 129
    sift_fused_kernel<<<grid, 256>>>(x, out);
}